// round 15
// baseline (speedup 1.0000x reference)
#include <cuda_runtime.h>

#define B_DIM 8
#define CIN 512
#define COUT 3
#define WDIM 512
#define HW 65536           // 256*256
#define CONV_CLAMP 256.0f

#define C_SPLIT 32         // rows streamed before the full barrier

// Staging for per-(batch, channel) coefficient triples:
//   g_m4[b*CIN+c] = (weight[0][c], weight[1][c], weight[2][c], 0) * styles[b][c]
__device__ float4 g_m4[B_DIM * CIN];

// Monotonic per-batch counters (never reset; epoch-derived targets keep graph
// replays deterministic). g_bar: all 64 CTAs of a batch arrive. g_bar4: only
// the 4 CTAs producing channels 0..31 (bx < 4) arrive.
__device__ unsigned int g_bar[B_DIM];
__device__ unsigned int g_bar4[B_DIM];

// Release-increment: orders all prior global writes before the counter bump.
__device__ __forceinline__ unsigned int atom_add_release(unsigned int* p,
                                                         unsigned int v)
{
    unsigned int old;
    asm volatile("atom.add.release.gpu.global.u32 %0, [%1], %2;"
                 : "=r"(old) : "l"(p), "r"(v) : "memory");
    return old;
}

// Acquire-load: orders the counter read before all subsequent global reads.
__device__ __forceinline__ unsigned int ld_acquire(const unsigned int* p)
{
    unsigned int v;
    asm volatile("ld.acquire.gpu.global.u32 %0, [%1];"
                 : "=r"(v) : "l"(p) : "memory");
    return v;
}

// ---------------------------------------------------------------------------
// Fused kernel = R14 (best: 157.47 total) + staged barrier.
// grid = (64, 8), block = 256; all 512 CTAs co-resident (4/SM x 148 = 592).
//
// Phase 1   : warp w computes channel c = bx*8+w, writes g_m4 (R7 scalar loads).
// Arrive    : release-add g_bar[b] (epoch E from returned value); CTAs with
//             bx < 4 also release-add g_bar4[b].
// Early wait: tid0 spins g_bar4[b] >= 4E (max-of-4 producer latency).
// Fill A    : smem coeffs c = 0..C_SPLIT.
// Loop A    : frozen body, FIXED bounds c = 0..C_SPLIT (~2.4us of streaming
//             that hides the remaining 60 producers' phase-1 window).
// Full wait : tid0 spins g_bar[b] >= 64E (normally already satisfied).
// Fill B    : smem coeffs c = C_SPLIT..512.
// Loop B    : frozen body, FIXED bounds c = C_SPLIT..512.
// Both loops are compile-time-bound (R8's failure was blockIdx-dependent
// bounds — avoided here).
// ---------------------------------------------------------------------------
__global__ void __launch_bounds__(256)
torgb_fused_kernel(const float* __restrict__ x,
                   const float* __restrict__ w,
                   const float* __restrict__ weight,
                   const float* __restrict__ bias,
                   const float* __restrict__ affine_w,
                   const float* __restrict__ affine_b,
                   float* __restrict__ out)
{
    __shared__ float m0[CIN];
    __shared__ float m1[CIN];
    __shared__ float m2[CIN];
    __shared__ unsigned int s_epoch;

    const int b    = blockIdx.y;
    const int bx   = blockIdx.x;
    const int tid  = threadIdx.x;
    const int warp = tid >> 5;
    const int lane = tid & 31;

    // ---- Phase 1: compute this CTA's 8 coefficients (c = bx*8 + warp) ----
    {
        const int c = bx * 8 + warp;
        const float* __restrict__ arow = affine_w + (size_t)c * WDIM;
        const float* __restrict__ wrow = w + (size_t)b * WDIM;
        float sum = 0.0f;
#pragma unroll
        for (int j = 0; j < WDIM / 32; ++j) {
            const int k = lane + 32 * j;
            sum = fmaf(__ldg(&arow[k]), __ldg(&wrow[k]), sum);
        }
#pragma unroll
        for (int off = 16; off > 0; off >>= 1)
            sum += __shfl_xor_sync(0xffffffffu, sum, off);

        if (lane == 0) {
            const float affine_gain = 1.0f / sqrtf((float)WDIM);
            const float cin_gain    = 1.0f / sqrtf((float)CIN);
            const float style = (sum * affine_gain + affine_b[c]) * cin_gain;
            float4 m;
            m.x = weight[0 * CIN + c] * style;
            m.y = weight[1 * CIN + c] * style;
            m.z = weight[2 * CIN + c] * style;
            m.w = 0.0f;
            g_m4[b * CIN + c] = m;
        }
    }
    __syncthreads();                 // all warps done writing g_m4

    // ---- Arrive (release) on both counters; derive epoch ----
    if (tid == 0) {
        const unsigned int start = atom_add_release(&g_bar[b], 1u);
        const unsigned int E = start / 64u + 1u;
        s_epoch = E;
        if (bx < 4)
            atom_add_release(&g_bar4[b], 1u);
        // Early wait: producers of channels 0..31 only.
        const unsigned int t4 = 4u * E;
        while (ld_acquire(&g_bar4[b]) < t4)
            __nanosleep(32);
    }
    __syncthreads();

    // ---- Fill coeffs for c = 0..C_SPLIT ----
    if (tid < C_SPLIT) {
        const float4 m = __ldcg(&g_m4[b * CIN + tid]);
        m0[tid] = m.x;
        m1[tid] = m.y;
        m2[tid] = m.z;
    }
    __syncthreads();

    const int hw4 = bx * blockDim.x + tid;    // index in float4 units
    const float4* __restrict__ x4 =
        (const float4*)(x + (size_t)b * CIN * HW);

    float4 a0 = make_float4(0.f, 0.f, 0.f, 0.f);
    float4 a1 = make_float4(0.f, 0.f, 0.f, 0.f);
    float4 a2 = make_float4(0.f, 0.f, 0.f, 0.f);

#define FMA3(xv, c)                                                       \
    {                                                                     \
        const float c0 = m0[(c)];                                         \
        const float c1 = m1[(c)];                                         \
        const float c2 = m2[(c)];                                         \
        a0.x = fmaf((xv).x, c0, a0.x); a0.y = fmaf((xv).y, c0, a0.y);     \
        a0.z = fmaf((xv).z, c0, a0.z); a0.w = fmaf((xv).w, c0, a0.w);     \
        a1.x = fmaf((xv).x, c1, a1.x); a1.y = fmaf((xv).y, c1, a1.y);     \
        a1.z = fmaf((xv).z, c1, a1.z); a1.w = fmaf((xv).w, c1, a1.w);     \
        a2.x = fmaf((xv).x, c2, a2.x); a2.y = fmaf((xv).y, c2, a2.y);     \
        a2.z = fmaf((xv).z, c2, a2.z); a2.w = fmaf((xv).w, c2, a2.w);     \
    }

    // ---- Loop A: fixed bounds 0..C_SPLIT (hides remaining producers) ----
#pragma unroll 4
    for (int c = 0; c < C_SPLIT; ++c) {
        const float4 xv = __ldcs(&x4[(size_t)c * (HW / 4) + hw4]);
        FMA3(xv, c)
    }

    // ---- Full wait (normally already satisfied) ----
    if (tid == 0) {
        const unsigned int t64 = 64u * s_epoch;
        while (ld_acquire(&g_bar[b]) < t64)
            __nanosleep(32);
    }
    __syncthreads();

    // ---- Fill coeffs for c = C_SPLIT..512 ----
    for (int c = C_SPLIT + tid; c < CIN; c += blockDim.x) {
        const float4 m = __ldcg(&g_m4[b * CIN + c]);
        m0[c] = m.x;
        m1[c] = m.y;
        m2[c] = m.z;
    }
    __syncthreads();

    // ---- Loop B: fixed bounds C_SPLIT..512 (frozen body) ----
#pragma unroll 4
    for (int c = C_SPLIT; c < CIN; ++c) {
        const float4 xv = __ldcs(&x4[(size_t)c * (HW / 4) + hw4]);
        FMA3(xv, c)
    }
#undef FMA3

    const float bv0 = bias[0];
    const float bv1 = bias[1];
    const float bv2 = bias[2];

#define CLAMP1(v) fminf(fmaxf((v), -CONV_CLAMP), CONV_CLAMP)
    float4 o0 = make_float4(CLAMP1(a0.x + bv0), CLAMP1(a0.y + bv0),
                            CLAMP1(a0.z + bv0), CLAMP1(a0.w + bv0));
    float4 o1 = make_float4(CLAMP1(a1.x + bv1), CLAMP1(a1.y + bv1),
                            CLAMP1(a1.z + bv1), CLAMP1(a1.w + bv1));
    float4 o2 = make_float4(CLAMP1(a2.x + bv2), CLAMP1(a2.y + bv2),
                            CLAMP1(a2.z + bv2), CLAMP1(a2.w + bv2));
#undef CLAMP1

    float4* __restrict__ out4 = (float4*)out;
    const size_t obase = (size_t)b * COUT * (HW / 4);
    __stcs(&out4[obase + 0 * (HW / 4) + hw4], o0);
    __stcs(&out4[obase + 1 * (HW / 4) + hw4], o1);
    __stcs(&out4[obase + 2 * (HW / 4) + hw4], o2);
}

// ---------------------------------------------------------------------------
// Launch
//   d_in[0] = x        [B, CIN, H, W]  f32
//   d_in[1] = w        [B, WDIM]       f32
//   d_in[2] = weight   [COUT, CIN,1,1] f32
//   d_in[3] = bias     [COUT]          f32
//   d_in[4] = affine_w [CIN, WDIM]     f32
//   d_in[5] = affine_b [CIN]           f32
// ---------------------------------------------------------------------------
extern "C" void kernel_launch(void* const* d_in, const int* in_sizes, int n_in,
                              void* d_out, int out_size)
{
    const float* x        = (const float*)d_in[0];
    const float* w        = (const float*)d_in[1];
    const float* weight   = (const float*)d_in[2];
    const float* bias     = (const float*)d_in[3];
    const float* affine_w = (const float*)d_in[4];
    const float* affine_b = (const float*)d_in[5];
    float* out = (float*)d_out;

    dim3 cgrid(HW / 4 / 256, B_DIM);
    torgb_fused_kernel<<<cgrid, 256>>>(x, w, weight, bias,
                                       affine_w, affine_b, out);
}

// round 16
// speedup vs baseline: 1.1822x; 1.1822x over previous
#include <cuda_runtime.h>

#define B_DIM 8
#define CIN 512
#define COUT 3
#define WDIM 512
#define HW 65536           // 256*256
#define CONV_CLAMP 256.0f

// Staging for per-(batch, channel) coefficient triples:
//   g_m4[b*CIN+c] = (weight[0][c], weight[1][c], weight[2][c], 0) * styles[b][c]
__device__ float4 g_m4[B_DIM * CIN];

// Per-batch arrival counters (monotonic across graph replays; cohort = 64 CTAs.
// target = (start/64+1)*64, so no reset is needed -> deterministic per run).
__device__ unsigned int g_bar[B_DIM];

// Release-increment: orders all prior global writes before the counter bump.
__device__ __forceinline__ unsigned int atom_add_release(unsigned int* p,
                                                         unsigned int v)
{
    unsigned int old;
    asm volatile("atom.add.release.gpu.global.u32 %0, [%1], %2;"
                 : "=r"(old) : "l"(p), "r"(v) : "memory");
    return old;
}

// Acquire-load: orders the counter read before all subsequent global reads.
__device__ __forceinline__ unsigned int ld_acquire(const unsigned int* p)
{
    unsigned int v;
    asm volatile("ld.acquire.gpu.global.u32 %0, [%1];"
                 : "=r"(v) : "l"(p) : "memory");
    return v;
}

// ---------------------------------------------------------------------------
// FINAL KERNEL (= R14, best of 15 rounds: 157.47us total).
//
// Design facts established over the session (GB300, sm_103a):
//  * Workload is a pure HBM read stream: 1.074GB of x read once; roofline
//    floor ~152.5us at the measured 7.09TB/s streaming rate.
//  * Geometry optimum: grid (64,8) x 256 threads, 1 float4 column/thread.
//    (1024x128 -> 76% DRAM; 256x256x2cols -> 51%; this -> 89.5% steady.)
//  * Stream loop must be ONE fixed-bound 0..512 loop with exactly this body
//    (LDS.32 coeffs, unroll 4, __ldcs/__stcs, regs~40). Splitting it or
//    widening loads collapses DRAM to ~75% (verified 4x).
//  * Styles fused via per-batch release/acquire spin barrier; all 512 CTAs
//    co-resident (4/SM x 148 = 592 slots) so the spin cannot deadlock.
//    No overlap trick (prefetch/preload/split/P-C roles) beat this.
// ---------------------------------------------------------------------------
__global__ void __launch_bounds__(256)
torgb_fused_kernel(const float* __restrict__ x,
                   const float* __restrict__ w,
                   const float* __restrict__ weight,
                   const float* __restrict__ bias,
                   const float* __restrict__ affine_w,
                   const float* __restrict__ affine_b,
                   float* __restrict__ out)
{
    __shared__ float m0[CIN];
    __shared__ float m1[CIN];
    __shared__ float m2[CIN];

    const int b    = blockIdx.y;
    const int bx   = blockIdx.x;
    const int tid  = threadIdx.x;
    const int warp = tid >> 5;
    const int lane = tid & 31;

    // ---- Phase 1: compute this CTA's 8 coefficients (c = bx*8 + warp) ----
    //      Scalar loads (float4 here measurably hurts — R10/R13).
    {
        const int c = bx * 8 + warp;
        const float* __restrict__ arow = affine_w + (size_t)c * WDIM;
        const float* __restrict__ wrow = w + (size_t)b * WDIM;
        float sum = 0.0f;
#pragma unroll
        for (int j = 0; j < WDIM / 32; ++j) {
            const int k = lane + 32 * j;
            sum = fmaf(__ldg(&arow[k]), __ldg(&wrow[k]), sum);
        }
#pragma unroll
        for (int off = 16; off > 0; off >>= 1)
            sum += __shfl_xor_sync(0xffffffffu, sum, off);

        if (lane == 0) {
            const float affine_gain = 1.0f / sqrtf((float)WDIM);
            const float cin_gain    = 1.0f / sqrtf((float)CIN);
            const float style = (sum * affine_gain + affine_b[c]) * cin_gain;
            float4 m;
            m.x = weight[0 * CIN + c] * style;
            m.y = weight[1 * CIN + c] * style;
            m.z = weight[2 * CIN + c] * style;
            m.w = 0.0f;
            g_m4[b * CIN + c] = m;
        }
    }
    __syncthreads();                 // all warps done writing g_m4

    // ---- Per-batch barrier (release/acquire atomics, no MEMBAR.GPU) ----
    if (tid == 0) {
        const unsigned int start  = atom_add_release(&g_bar[b], 1u);
        const unsigned int target = (start / 64u + 1u) * 64u;
        while (ld_acquire(&g_bar[b]) < target)
            __nanosleep(32);
    }
    __syncthreads();

    // ---- Coefficient fill for batch b (L2 via __ldcg) ----
    for (int c = tid; c < CIN; c += blockDim.x) {
        const float4 m = __ldcg(&g_m4[b * CIN + c]);
        m0[c] = m.x;
        m1[c] = m.y;
        m2[c] = m.z;
    }
    __syncthreads();

    // ---- Phase 2: the frozen streaming loop (single fixed 0..512) ----
    const int hw4 = bx * blockDim.x + tid;    // index in float4 units
    const float4* __restrict__ x4 =
        (const float4*)(x + (size_t)b * CIN * HW);

    float4 a0 = make_float4(0.f, 0.f, 0.f, 0.f);
    float4 a1 = make_float4(0.f, 0.f, 0.f, 0.f);
    float4 a2 = make_float4(0.f, 0.f, 0.f, 0.f);

#pragma unroll 4
    for (int c = 0; c < CIN; ++c) {
        const float4 xv = __ldcs(&x4[(size_t)c * (HW / 4) + hw4]);
        const float c0 = m0[c];
        const float c1 = m1[c];
        const float c2 = m2[c];
        a0.x = fmaf(xv.x, c0, a0.x); a0.y = fmaf(xv.y, c0, a0.y);
        a0.z = fmaf(xv.z, c0, a0.z); a0.w = fmaf(xv.w, c0, a0.w);
        a1.x = fmaf(xv.x, c1, a1.x); a1.y = fmaf(xv.y, c1, a1.y);
        a1.z = fmaf(xv.z, c1, a1.z); a1.w = fmaf(xv.w, c1, a1.w);
        a2.x = fmaf(xv.x, c2, a2.x); a2.y = fmaf(xv.y, c2, a2.y);
        a2.z = fmaf(xv.z, c2, a2.z); a2.w = fmaf(xv.w, c2, a2.w);
    }

    const float bv0 = bias[0];
    const float bv1 = bias[1];
    const float bv2 = bias[2];

#define CLAMP1(v) fminf(fmaxf((v), -CONV_CLAMP), CONV_CLAMP)
    float4 o0 = make_float4(CLAMP1(a0.x + bv0), CLAMP1(a0.y + bv0),
                            CLAMP1(a0.z + bv0), CLAMP1(a0.w + bv0));
    float4 o1 = make_float4(CLAMP1(a1.x + bv1), CLAMP1(a1.y + bv1),
                            CLAMP1(a1.z + bv1), CLAMP1(a1.w + bv1));
    float4 o2 = make_float4(CLAMP1(a2.x + bv2), CLAMP1(a2.y + bv2),
                            CLAMP1(a2.z + bv2), CLAMP1(a2.w + bv2));
#undef CLAMP1

    float4* __restrict__ out4 = (float4*)out;
    const size_t obase = (size_t)b * COUT * (HW / 4);
    __stcs(&out4[obase + 0 * (HW / 4) + hw4], o0);
    __stcs(&out4[obase + 1 * (HW / 4) + hw4], o1);
    __stcs(&out4[obase + 2 * (HW / 4) + hw4], o2);
}

// ---------------------------------------------------------------------------
// Launch
//   d_in[0] = x        [B, CIN, H, W]  f32
//   d_in[1] = w        [B, WDIM]       f32
//   d_in[2] = weight   [COUT, CIN,1,1] f32
//   d_in[3] = bias     [COUT]          f32
//   d_in[4] = affine_w [CIN, WDIM]     f32
//   d_in[5] = affine_b [CIN]           f32
// ---------------------------------------------------------------------------
extern "C" void kernel_launch(void* const* d_in, const int* in_sizes, int n_in,
                              void* d_out, int out_size)
{
    const float* x        = (const float*)d_in[0];
    const float* w        = (const float*)d_in[1];
    const float* weight   = (const float*)d_in[2];
    const float* bias     = (const float*)d_in[3];
    const float* affine_w = (const float*)d_in[4];
    const float* affine_b = (const float*)d_in[5];
    float* out = (float*)d_out;

    dim3 cgrid(HW / 4 / 256, B_DIM);
    torgb_fused_kernel<<<cgrid, 256>>>(x, w, weight, bias,
                                       affine_w, affine_b, out);
}

// round 17
// speedup vs baseline: 1.1853x; 1.0026x over previous
#include <cuda_runtime.h>

#define B_DIM 8
#define CIN 512
#define COUT 3
#define WDIM 512
#define HW 65536           // 256*256
#define CONV_CLAMP 256.0f

// Staging for per-(batch, channel) coefficient triples:
//   g_m4[b*CIN+c] = (weight[0][c], weight[1][c], weight[2][c], 0) * styles[b][c]
__device__ float4 g_m4[B_DIM * CIN];

// Per-batch arrival counters (monotonic across graph replays; cohort = 64 CTAs.
// target = (start/64+1)*64, so no reset is needed -> deterministic per run).
__device__ unsigned int g_bar[B_DIM];

// Release-increment: orders all prior global writes before the counter bump.
__device__ __forceinline__ unsigned int atom_add_release(unsigned int* p,
                                                         unsigned int v)
{
    unsigned int old;
    asm volatile("atom.add.release.gpu.global.u32 %0, [%1], %2;"
                 : "=r"(old) : "l"(p), "r"(v) : "memory");
    return old;
}

// Acquire-load: orders the counter read before all subsequent global reads.
__device__ __forceinline__ unsigned int ld_acquire(const unsigned int* p)
{
    unsigned int v;
    asm volatile("ld.acquire.gpu.global.u32 %0, [%1];"
                 : "=r"(v) : "l"(p) : "memory");
    return v;
}

// ---------------------------------------------------------------------------
// FINAL KERNEL (R14 configuration — best measured draw 157.47us; run-to-run
// noise calibrated at +/-1.2us by a byte-identical re-bench).
//
// Session-established facts (GB300, sm_103a):
//  * Pure HBM read stream: 1.074GB of x read once; stream steady-state
//    151.9us @ 89.5% DRAM / 7.09TB/s — the achievable ceiling for this
//    pattern (every perturbation collapses it to 75% or below).
//  * Geometry optimum: grid (64,8) x 256 threads, 1 float4 column/thread.
//  * Stream loop: ONE fixed-bound 0..512 loop, scalar smem coeff loads,
//    unroll 4, __ldcs/__stcs, regs~40. Frozen — verified fragile 5x.
//  * Styles fused via per-batch release/acquire spin barrier (all 512 CTAs
//    co-resident: 4/SM x 148 = 592 slots -> deadlock-free). The ~3.5us
//    prologue is irreducible: prefetch, preload, producer/consumer split,
//    staged barriers, and fence elision all failed to beat it.
// ---------------------------------------------------------------------------
__global__ void __launch_bounds__(256)
torgb_fused_kernel(const float* __restrict__ x,
                   const float* __restrict__ w,
                   const float* __restrict__ weight,
                   const float* __restrict__ bias,
                   const float* __restrict__ affine_w,
                   const float* __restrict__ affine_b,
                   float* __restrict__ out)
{
    __shared__ float m0[CIN];
    __shared__ float m1[CIN];
    __shared__ float m2[CIN];

    const int b    = blockIdx.y;
    const int bx   = blockIdx.x;
    const int tid  = threadIdx.x;
    const int warp = tid >> 5;
    const int lane = tid & 31;

    // ---- Phase 1: compute this CTA's 8 coefficients (c = bx*8 + warp) ----
    //      Scalar loads (float4 here measurably hurts — R10/R13).
    {
        const int c = bx * 8 + warp;
        const float* __restrict__ arow = affine_w + (size_t)c * WDIM;
        const float* __restrict__ wrow = w + (size_t)b * WDIM;
        float sum = 0.0f;
#pragma unroll
        for (int j = 0; j < WDIM / 32; ++j) {
            const int k = lane + 32 * j;
            sum = fmaf(__ldg(&arow[k]), __ldg(&wrow[k]), sum);
        }
#pragma unroll
        for (int off = 16; off > 0; off >>= 1)
            sum += __shfl_xor_sync(0xffffffffu, sum, off);

        if (lane == 0) {
            const float affine_gain = 1.0f / sqrtf((float)WDIM);
            const float cin_gain    = 1.0f / sqrtf((float)CIN);
            const float style = (sum * affine_gain + affine_b[c]) * cin_gain;
            float4 m;
            m.x = weight[0 * CIN + c] * style;
            m.y = weight[1 * CIN + c] * style;
            m.z = weight[2 * CIN + c] * style;
            m.w = 0.0f;
            g_m4[b * CIN + c] = m;
        }
    }
    __syncthreads();                 // all warps done writing g_m4

    // ---- Per-batch barrier (release/acquire atomics, no MEMBAR.GPU) ----
    if (tid == 0) {
        const unsigned int start  = atom_add_release(&g_bar[b], 1u);
        const unsigned int target = (start / 64u + 1u) * 64u;
        while (ld_acquire(&g_bar[b]) < target)
            __nanosleep(32);
    }
    __syncthreads();

    // ---- Coefficient fill for batch b (L2 via __ldcg) ----
    for (int c = tid; c < CIN; c += blockDim.x) {
        const float4 m = __ldcg(&g_m4[b * CIN + c]);
        m0[c] = m.x;
        m1[c] = m.y;
        m2[c] = m.z;
    }
    __syncthreads();

    // ---- Phase 2: the frozen streaming loop (single fixed 0..512) ----
    const int hw4 = bx * blockDim.x + tid;    // index in float4 units
    const float4* __restrict__ x4 =
        (const float4*)(x + (size_t)b * CIN * HW);

    float4 a0 = make_float4(0.f, 0.f, 0.f, 0.f);
    float4 a1 = make_float4(0.f, 0.f, 0.f, 0.f);
    float4 a2 = make_float4(0.f, 0.f, 0.f, 0.f);

#pragma unroll 4
    for (int c = 0; c < CIN; ++c) {
        const float4 xv = __ldcs(&x4[(size_t)c * (HW / 4) + hw4]);
        const float c0 = m0[c];
        const float c1 = m1[c];
        const float c2 = m2[c];
        a0.x = fmaf(xv.x, c0, a0.x); a0.y = fmaf(xv.y, c0, a0.y);
        a0.z = fmaf(xv.z, c0, a0.z); a0.w = fmaf(xv.w, c0, a0.w);
        a1.x = fmaf(xv.x, c1, a1.x); a1.y = fmaf(xv.y, c1, a1.y);
        a1.z = fmaf(xv.z, c1, a1.z); a1.w = fmaf(xv.w, c1, a1.w);
        a2.x = fmaf(xv.x, c2, a2.x); a2.y = fmaf(xv.y, c2, a2.y);
        a2.z = fmaf(xv.z, c2, a2.z); a2.w = fmaf(xv.w, c2, a2.w);
    }

    const float bv0 = bias[0];
    const float bv1 = bias[1];
    const float bv2 = bias[2];

#define CLAMP1(v) fminf(fmaxf((v), -CONV_CLAMP), CONV_CLAMP)
    float4 o0 = make_float4(CLAMP1(a0.x + bv0), CLAMP1(a0.y + bv0),
                            CLAMP1(a0.z + bv0), CLAMP1(a0.w + bv0));
    float4 o1 = make_float4(CLAMP1(a1.x + bv1), CLAMP1(a1.y + bv1),
                            CLAMP1(a1.z + bv1), CLAMP1(a1.w + bv1));
    float4 o2 = make_float4(CLAMP1(a2.x + bv2), CLAMP1(a2.y + bv2),
                            CLAMP1(a2.z + bv2), CLAMP1(a2.w + bv2));
#undef CLAMP1

    float4* __restrict__ out4 = (float4*)out;
    const size_t obase = (size_t)b * COUT * (HW / 4);
    __stcs(&out4[obase + 0 * (HW / 4) + hw4], o0);
    __stcs(&out4[obase + 1 * (HW / 4) + hw4], o1);
    __stcs(&out4[obase + 2 * (HW / 4) + hw4], o2);
}

// ---------------------------------------------------------------------------
// Launch
//   d_in[0] = x        [B, CIN, H, W]  f32
//   d_in[1] = w        [B, WDIM]       f32
//   d_in[2] = weight   [COUT, CIN,1,1] f32
//   d_in[3] = bias     [COUT]          f32
//   d_in[4] = affine_w [CIN, WDIM]     f32
//   d_in[5] = affine_b [CIN]           f32
// ---------------------------------------------------------------------------
extern "C" void kernel_launch(void* const* d_in, const int* in_sizes, int n_in,
                              void* d_out, int out_size)
{
    const float* x        = (const float*)d_in[0];
    const float* w        = (const float*)d_in[1];
    const float* weight   = (const float*)d_in[2];
    const float* bias     = (const float*)d_in[3];
    const float* affine_w = (const float*)d_in[4];
    const float* affine_b = (const float*)d_in[5];
    float* out = (float*)d_out;

    dim3 cgrid(HW / 4 / 256, B_DIM);
    torgb_fused_kernel<<<cgrid, 256>>>(x, w, weight, bias,
                                       affine_w, affine_b, out);
}